// round 13
// baseline (speedup 1.0000x reference)
#include <cuda_runtime.h>
#include <cuda_bf16.h>
#include <math.h>

#define Bsz   16
#define CDIM  384
#define HH    56
#define WW    56
#define NTOK  3136          // 56*56
#define TOKS  (Bsz*NTOK)    // 50176
#define NHEAD 8
#define SPLIT 128
#define HID   1536
#define RR    192
#define NSPL  7             // attention token splits (49 tiles of 64 = 7x7)

typedef unsigned long long ull;

// ---------------- scratch (device globals; no allocations allowed) ----------
__device__ float g_big[(size_t)TOKS*1152];     // bf16 qkv alias lives here
__device__ float g_s1 [(size_t)Bsz*SPLIT*NTOK];
__device__ float g_s2 [(size_t)Bsz*SPLIT*NTOK];
__device__ float g_xf2[(size_t)TOKS*CDIM];
__device__ __nv_bfloat16 g_y16 [(size_t)TOKS*CDIM];
__device__ __nv_bfloat16 g_att16[(size_t)TOKS*CDIM];
__device__ __nv_bfloat16 g_t116[(size_t)TOKS*RR];
__device__ __nv_bfloat16 g_t216[(size_t)TOKS*RR];
__device__ __nv_bfloat16 g_h16 [(size_t)TOKS*HID];
// attention staging
__device__ float  g_gramP[(size_t)NSPL*128*2304];
__device__ float  g_qsqP [(size_t)NSPL*128*48];
__device__ float  g_ksqP [(size_t)NSPL*128*48];
__device__ float2 g_attn2[(size_t)128*2304];
// transposed bf16 weights, [N, K] K-major rows
__device__ __nv_bfloat16 g_wq [1152*384];
__device__ __nv_bfloat16 g_wp [384*384];
__device__ __nv_bfloat16 g_w1d[192*384];
__device__ __nv_bfloat16 g_w1u[1536*192];
__device__ __nv_bfloat16 g_w2d[192*1536];
__device__ __nv_bfloat16 g_w2u[384*192];

// ---------------- helpers ----------------------------------------------------
__device__ __forceinline__ unsigned smem_u32(const void* p) {
    unsigned a;
    asm("{ .reg .u64 t; cvta.to.shared.u64 t, %1; cvt.u32.u64 %0, t; }"
        : "=r"(a) : "l"(p));
    return a;
}
__device__ __forceinline__ void cpasync16(unsigned dst, const void* src) {
    asm volatile("cp.async.cg.shared.global [%0], [%1], 16;" :: "r"(dst), "l"(src));
}
#define CP_COMMIT() asm volatile("cp.async.commit_group;" ::: "memory")
__device__ __forceinline__ void ldm_x4(unsigned& r0, unsigned& r1, unsigned& r2,
                                       unsigned& r3, unsigned addr) {
    asm volatile("ldmatrix.sync.aligned.m8n8.x4.shared.b16 {%0,%1,%2,%3}, [%4];"
                 : "=r"(r0), "=r"(r1), "=r"(r2), "=r"(r3) : "r"(addr));
}
__device__ __forceinline__ void mma_bf16(float* d, const unsigned* a,
                                         unsigned b0, unsigned b1) {
    asm volatile(
        "mma.sync.aligned.m16n8k16.row.col.f32.bf16.bf16.f32 "
        "{%0,%1,%2,%3}, {%4,%5,%6,%7}, {%8,%9}, {%0,%1,%2,%3};\n"
        : "+f"(d[0]), "+f"(d[1]), "+f"(d[2]), "+f"(d[3])
        : "r"(a[0]), "r"(a[1]), "r"(a[2]), "r"(a[3]), "r"(b0), "r"(b1));
}
// packed f32x2 (sm_100+ baseline PTX, not arch-'a'-gated)
__device__ __forceinline__ ull fma2(ull a, ull b, ull c) {
    ull d;
    asm("fma.rn.f32x2 %0, %1, %2, %3;" : "=l"(d) : "l"(a), "l"(b), "l"(c));
    return d;
}
__device__ __forceinline__ ull pk(float lo, float hi) {
    ull r;
    asm("mov.b64 %0, {%1, %2};" : "=l"(r) : "f"(lo), "f"(hi));
    return r;
}
__device__ __forceinline__ void unpk(float& lo, float& hi, ull v) {
    asm("mov.b64 {%0, %1}, %2;" : "=f"(lo), "=f"(hi) : "l"(v));
}

#define ASTR 40   // padded row stride (bf16): 32 data + 8 pad -> conflict-free ldmatrix

// ============ bf16 GEMM, 128x128 tile (N % 128 == 0), 3-stage pipeline =======
__global__ __launch_bounds__(256) void bgemm128(
    const __nv_bfloat16* __restrict__ A, const __nv_bfloat16* __restrict__ Bw,
    float* __restrict__ Cf, __nv_bfloat16* __restrict__ Cb,
    int M, int N, int K,
    const float* __restrict__ bias, const float* __restrict__ res, int do_gelu)
{
    __shared__ __align__(16) __nv_bfloat16 As[3][128][ASTR];
    __shared__ __align__(16) __nv_bfloat16 Bs[3][128][ASTR];
    int tid = threadIdx.x, lane = tid & 31, wid = tid >> 5;
    int wm = wid & 1, wn = wid >> 1;
    const __nv_bfloat16* Ab = A  + (size_t)blockIdx.y * 128 * K;
    const __nv_bfloat16* Bb = Bw + (size_t)blockIdx.x * 128 * K;

    float acc[4][4][4];
#pragma unroll
    for (int mf = 0; mf < 4; mf++)
#pragma unroll
        for (int nf = 0; nf < 4; nf++)
#pragma unroll
            for (int i = 0; i < 4; i++) acc[mf][nf][i] = 0.f;

    int nk = K >> 5;
    int lrow = tid >> 2, lseg = tid & 3;

#pragma unroll
    for (int pc = 0; pc < 2; pc++) {
        long kb = (long)pc * 32;
#pragma unroll
        for (int i = 0; i < 2; i++) {
            int row = lrow + i * 64;
            cpasync16(smem_u32(&As[pc][row][lseg * 8]), Ab + (size_t)row * K + kb + lseg * 8);
            cpasync16(smem_u32(&Bs[pc][row][lseg * 8]), Bb + (size_t)row * K + kb + lseg * 8);
        }
        CP_COMMIT();
    }

    for (int kc = 0; kc < nk; kc++) {
        int buf = kc % 3;
        if (kc + 1 < nk) asm volatile("cp.async.wait_group 1;" ::: "memory");
        else             asm volatile("cp.async.wait_group 0;" ::: "memory");
        __syncthreads();
        if (kc + 2 < nk) {
            int nbuf = (kc + 2) % 3;
            long kb = (long)(kc + 2) * 32;
#pragma unroll
            for (int i = 0; i < 2; i++) {
                int row = lrow + i * 64;
                cpasync16(smem_u32(&As[nbuf][row][lseg * 8]),
                          Ab + (size_t)row * K + kb + lseg * 8);
                cpasync16(smem_u32(&Bs[nbuf][row][lseg * 8]),
                          Bb + (size_t)row * K + kb + lseg * 8);
            }
            CP_COMMIT();
        }

#pragma unroll
        for (int ks = 0; ks < 2; ks++) {
            unsigned a[4][4], bb[4][2];
#pragma unroll
            for (int mf = 0; mf < 4; mf++) {
                int r = wm * 64 + mf * 16 + (lane & 15);
                int c = ks * 16 + (lane >> 4) * 8;
                ldm_x4(a[mf][0], a[mf][1], a[mf][2], a[mf][3],
                       smem_u32(&As[buf][r][c]));
            }
#pragma unroll
            for (int nh = 0; nh < 2; nh++) {
                int r = wn * 32 + nh * 16 + (lane >> 4) * 8 + (lane & 7);
                int c = ks * 16 + ((lane >> 3) & 1) * 8;
                unsigned r0, r1, r2, r3;
                ldm_x4(r0, r1, r2, r3, smem_u32(&Bs[buf][r][c]));
                bb[nh * 2][0] = r0; bb[nh * 2][1] = r1;
                bb[nh * 2 + 1][0] = r2; bb[nh * 2 + 1][1] = r3;
            }
#pragma unroll
            for (int mf = 0; mf < 4; mf++)
#pragma unroll
                for (int nf = 0; nf < 4; nf++)
                    mma_bf16(acc[mf][nf], a[mf], bb[nf][0], bb[nf][1]);
        }
    }

    int g = lane >> 2, t = lane & 3;
#pragma unroll
    for (int mf = 0; mf < 4; mf++)
#pragma unroll
        for (int nf = 0; nf < 4; nf++) {
            int col = blockIdx.x * 128 + wn * 32 + nf * 8 + 2 * t;
#pragma unroll
            for (int rr = 0; rr < 2; rr++) {
                int row = blockIdx.y * 128 + wm * 64 + mf * 16 + g + rr * 8;
                float v0 = acc[mf][nf][rr * 2 + 0];
                float v1 = acc[mf][nf][rr * 2 + 1];
                if (bias) { v0 += __ldg(&bias[col]); v1 += __ldg(&bias[col + 1]); }
                if (do_gelu) {
                    v0 = 0.5f * v0 * (1.f + erff(v0 * 0.70710678118f));
                    v1 = 0.5f * v1 * (1.f + erff(v1 * 0.70710678118f));
                }
                if (res) {
                    float2 rv = *(const float2*)(res + (size_t)row * N + col);
                    v0 += rv.x; v1 += rv.y;
                }
                if (Cf) {
                    float2 o; o.x = v0; o.y = v1;
                    *(float2*)(Cf + (size_t)row * N + col) = o;
                } else {
                    __nv_bfloat162 b2 = __floats2bfloat162_rn(v0, v1);
                    *(__nv_bfloat162*)(Cb + (size_t)row * N + col) = b2;
                }
            }
        }
}

// ============ proj GEMM: 128x128 tile, residual read from NCHW sources ======
__global__ __launch_bounds__(256) void bgemm128_resnchw(
    const __nv_bfloat16* __restrict__ A, const __nv_bfloat16* __restrict__ Bw,
    float* __restrict__ Cf, int M, int N, int K,
    const float* __restrict__ bias,
    const float* __restrict__ rx, const float* __restrict__ rs1,
    const float* __restrict__ rs2)
{
    __shared__ __align__(16) __nv_bfloat16 As[3][128][ASTR];
    __shared__ __align__(16) __nv_bfloat16 Bs[3][128][ASTR];
    int tid = threadIdx.x, lane = tid & 31, wid = tid >> 5;
    int wm = wid & 1, wn = wid >> 1;
    const __nv_bfloat16* Ab = A  + (size_t)blockIdx.y * 128 * K;
    const __nv_bfloat16* Bb = Bw + (size_t)blockIdx.x * 128 * K;

    float acc[4][4][4];
#pragma unroll
    for (int mf = 0; mf < 4; mf++)
#pragma unroll
        for (int nf = 0; nf < 4; nf++)
#pragma unroll
            for (int i = 0; i < 4; i++) acc[mf][nf][i] = 0.f;

    int nk = K >> 5;
    int lrow = tid >> 2, lseg = tid & 3;

#pragma unroll
    for (int pc = 0; pc < 2; pc++) {
        long kb = (long)pc * 32;
#pragma unroll
        for (int i = 0; i < 2; i++) {
            int row = lrow + i * 64;
            cpasync16(smem_u32(&As[pc][row][lseg * 8]), Ab + (size_t)row * K + kb + lseg * 8);
            cpasync16(smem_u32(&Bs[pc][row][lseg * 8]), Bb + (size_t)row * K + kb + lseg * 8);
        }
        CP_COMMIT();
    }

    for (int kc = 0; kc < nk; kc++) {
        int buf = kc % 3;
        if (kc + 1 < nk) asm volatile("cp.async.wait_group 1;" ::: "memory");
        else             asm volatile("cp.async.wait_group 0;" ::: "memory");
        __syncthreads();
        if (kc + 2 < nk) {
            int nbuf = (kc + 2) % 3;
            long kb = (long)(kc + 2) * 32;
#pragma unroll
            for (int i = 0; i < 2; i++) {
                int row = lrow + i * 64;
                cpasync16(smem_u32(&As[nbuf][row][lseg * 8]),
                          Ab + (size_t)row * K + kb + lseg * 8);
                cpasync16(smem_u32(&Bs[nbuf][row][lseg * 8]),
                          Bb + (size_t)row * K + kb + lseg * 8);
            }
            CP_COMMIT();
        }

#pragma unroll
        for (int ks = 0; ks < 2; ks++) {
            unsigned a[4][4], bb[4][2];
#pragma unroll
            for (int mf = 0; mf < 4; mf++) {
                int r = wm * 64 + mf * 16 + (lane & 15);
                int c = ks * 16 + (lane >> 4) * 8;
                ldm_x4(a[mf][0], a[mf][1], a[mf][2], a[mf][3],
                       smem_u32(&As[buf][r][c]));
            }
#pragma unroll
            for (int nh = 0; nh < 2; nh++) {
                int r = wn * 32 + nh * 16 + (lane >> 4) * 8 + (lane & 7);
                int c = ks * 16 + ((lane >> 3) & 1) * 8;
                unsigned r0, r1, r2, r3;
                ldm_x4(r0, r1, r2, r3, smem_u32(&Bs[buf][r][c]));
                bb[nh * 2][0] = r0; bb[nh * 2][1] = r1;
                bb[nh * 2 + 1][0] = r2; bb[nh * 2 + 1][1] = r3;
            }
#pragma unroll
            for (int mf = 0; mf < 4; mf++)
#pragma unroll
                for (int nf = 0; nf < 4; nf++)
                    mma_bf16(acc[mf][nf], a[mf], bb[nf][0], bb[nf][1]);
        }
    }

    int g = lane >> 2, t = lane & 3;
#pragma unroll
    for (int mf = 0; mf < 4; mf++)
#pragma unroll
        for (int nf = 0; nf < 4; nf++) {
            int col = blockIdx.x * 128 + wn * 32 + nf * 8 + 2 * t;
            float b0 = __ldg(&bias[col]), b1 = __ldg(&bias[col + 1]);
            // residual source base for this channel (col, col+1 = +NTOK)
#pragma unroll
            for (int rr = 0; rr < 2; rr++) {
                int row = blockIdx.y * 128 + wm * 64 + mf * 16 + g + rr * 8;
                int b2 = row / NTOK, n = row - b2 * NTOK;
                const float* src;
                if (col < 128)      src = rx  + ((size_t)b2 * CDIM  + col)        * NTOK + n;
                else if (col < 256) src = rs1 + ((size_t)b2 * SPLIT + (col-128)) * NTOK + n;
                else                src = rs2 + ((size_t)b2 * SPLIT + (col-256)) * NTOK + n;
                float v0 = acc[mf][nf][rr * 2 + 0] + b0 + src[0];
                float v1 = acc[mf][nf][rr * 2 + 1] + b1 + src[NTOK];
                float2 o; o.x = v0; o.y = v1;
                *(float2*)(Cf + (size_t)row * N + col) = o;
            }
        }
}

// ============ final GEMM: 128x128 tile, N=384, writes NCHW out directly ======
__global__ __launch_bounds__(256) void bgemm128_nchw(
    const __nv_bfloat16* __restrict__ A, const __nv_bfloat16* __restrict__ Bw,
    float* __restrict__ out, int M, int N, int K,
    const float* __restrict__ bias, const float* __restrict__ res)
{
    __shared__ __align__(16) __nv_bfloat16 As[3][128][ASTR];
    __shared__ __align__(16) __nv_bfloat16 Bs[3][128][ASTR];
    __shared__ float tbuf[32][132];
    int tid = threadIdx.x, lane = tid & 31, wid = tid >> 5;
    int wm = wid & 1, wn = wid >> 1;
    const __nv_bfloat16* Ab = A  + (size_t)blockIdx.y * 128 * K;
    const __nv_bfloat16* Bb = Bw + (size_t)blockIdx.x * 128 * K;

    float acc[4][4][4];
#pragma unroll
    for (int mf = 0; mf < 4; mf++)
#pragma unroll
        for (int nf = 0; nf < 4; nf++)
#pragma unroll
            for (int i = 0; i < 4; i++) acc[mf][nf][i] = 0.f;

    int nk = K >> 5;
    int lrow = tid >> 2, lseg = tid & 3;

#pragma unroll
    for (int pc = 0; pc < 2; pc++) {
        long kb = (long)pc * 32;
#pragma unroll
        for (int i = 0; i < 2; i++) {
            int row = lrow + i * 64;
            cpasync16(smem_u32(&As[pc][row][lseg * 8]), Ab + (size_t)row * K + kb + lseg * 8);
            cpasync16(smem_u32(&Bs[pc][row][lseg * 8]), Bb + (size_t)row * K + kb + lseg * 8);
        }
        CP_COMMIT();
    }

    for (int kc = 0; kc < nk; kc++) {
        int buf = kc % 3;
        if (kc + 1 < nk) asm volatile("cp.async.wait_group 1;" ::: "memory");
        else             asm volatile("cp.async.wait_group 0;" ::: "memory");
        __syncthreads();
        if (kc + 2 < nk) {
            int nbuf = (kc + 2) % 3;
            long kb = (long)(kc + 2) * 32;
#pragma unroll
            for (int i = 0; i < 2; i++) {
                int row = lrow + i * 64;
                cpasync16(smem_u32(&As[nbuf][row][lseg * 8]),
                          Ab + (size_t)row * K + kb + lseg * 8);
                cpasync16(smem_u32(&Bs[nbuf][row][lseg * 8]),
                          Bb + (size_t)row * K + kb + lseg * 8);
            }
            CP_COMMIT();
        }

#pragma unroll
        for (int ks = 0; ks < 2; ks++) {
            unsigned a[4][4], bb[4][2];
#pragma unroll
            for (int mf = 0; mf < 4; mf++) {
                int r = wm * 64 + mf * 16 + (lane & 15);
                int c = ks * 16 + (lane >> 4) * 8;
                ldm_x4(a[mf][0], a[mf][1], a[mf][2], a[mf][3],
                       smem_u32(&As[buf][r][c]));
            }
#pragma unroll
            for (int nh = 0; nh < 2; nh++) {
                int r = wn * 32 + nh * 16 + (lane >> 4) * 8 + (lane & 7);
                int c = ks * 16 + ((lane >> 3) & 1) * 8;
                unsigned r0, r1, r2, r3;
                ldm_x4(r0, r1, r2, r3, smem_u32(&Bs[buf][r][c]));
                bb[nh * 2][0] = r0; bb[nh * 2][1] = r1;
                bb[nh * 2 + 1][0] = r2; bb[nh * 2 + 1][1] = r3;
            }
#pragma unroll
            for (int mf = 0; mf < 4; mf++)
#pragma unroll
                for (int nf = 0; nf < 4; nf++)
                    mma_bf16(acc[mf][nf], a[mf], bb[nf][0], bb[nf][1]);
        }
    }

    // epilogue: bias + residual, then transpose through smem, write NCHW
    int g = lane >> 2, t = lane & 3;
    __syncthreads();
#pragma unroll
    for (int p = 0; p < 4; p++) {
        if (wn == p) {
#pragma unroll
            for (int mf = 0; mf < 4; mf++)
#pragma unroll
                for (int nf = 0; nf < 4; nf++) {
                    int lcol = nf * 8 + 2 * t;
                    int col = blockIdx.x * 128 + p * 32 + lcol;
#pragma unroll
                    for (int rr = 0; rr < 2; rr++) {
                        int lrow2 = wm * 64 + mf * 16 + g + rr * 8;
                        int grow = blockIdx.y * 128 + lrow2;
                        float v0 = acc[mf][nf][rr * 2 + 0] + __ldg(&bias[col]);
                        float v1 = acc[mf][nf][rr * 2 + 1] + __ldg(&bias[col + 1]);
                        float2 rv = *(const float2*)(res + (size_t)grow * N + col);
                        v0 += rv.x; v1 += rv.y;
                        tbuf[lcol][lrow2] = v0;
                        tbuf[lcol + 1][lrow2] = v1;
                    }
                }
        }
        __syncthreads();
#pragma unroll
        for (int q = 0; q < 16; q++) {
            int lin = tid + q * 256;
            int ch = lin >> 7, row = lin & 127;
            int tok = blockIdx.y * 128 + row;
            int bb2 = tok / NTOK, n = tok - bb2 * NTOK;
            out[((size_t)bb2 * CDIM + blockIdx.x * 128 + p * 32 + ch) * NTOK + n] =
                tbuf[ch][row];
        }
        __syncthreads();
    }
}

// ============ bf16 GEMM, 128x64 tile (for N = 192), 3-stage pipeline =========
__global__ __launch_bounds__(256) void bgemm(
    const __nv_bfloat16* __restrict__ A, const __nv_bfloat16* __restrict__ Bw,
    float* __restrict__ Cf, __nv_bfloat16* __restrict__ Cb,
    int M, int N, int K,
    const float* __restrict__ bias, const float* __restrict__ res, int do_gelu)
{
    __shared__ __align__(16) __nv_bfloat16 As[3][128][ASTR];
    __shared__ __align__(16) __nv_bfloat16 Bs[3][64][ASTR];
    int tid = threadIdx.x, lane = tid & 31, wid = tid >> 5;
    int wm = wid & 3, wn = wid >> 2;
    const __nv_bfloat16* Ab = A  + (size_t)blockIdx.y * 128 * K;
    const __nv_bfloat16* Bb = Bw + (size_t)blockIdx.x * 64 * K;

    float acc[2][4][4];
#pragma unroll
    for (int mf = 0; mf < 2; mf++)
#pragma unroll
        for (int nf = 0; nf < 4; nf++)
#pragma unroll
            for (int i = 0; i < 4; i++) acc[mf][nf][i] = 0.f;

    int nk = K >> 5;
    int lrow = tid >> 2, lseg = tid & 3;

#pragma unroll
    for (int pc = 0; pc < 2; pc++) {
        long kb = (long)pc * 32;
#pragma unroll
        for (int i = 0; i < 2; i++) {
            int row = lrow + i * 64;
            cpasync16(smem_u32(&As[pc][row][lseg * 8]),
                      Ab + (size_t)row * K + kb + lseg * 8);
        }
        if (lrow < 64)
            cpasync16(smem_u32(&Bs[pc][lrow][lseg * 8]),
                      Bb + (size_t)lrow * K + kb + lseg * 8);
        CP_COMMIT();
    }

    for (int kc = 0; kc < nk; kc++) {
        int buf = kc % 3;
        if (kc + 1 < nk) asm volatile("cp.async.wait_group 1;" ::: "memory");
        else             asm volatile("cp.async.wait_group 0;" ::: "memory");
        __syncthreads();
        if (kc + 2 < nk) {
            int nbuf = (kc + 2) % 3;
            long kb = (long)(kc + 2) * 32;
#pragma unroll
            for (int i = 0; i < 2; i++) {
                int row = lrow + i * 64;
                cpasync16(smem_u32(&As[nbuf][row][lseg * 8]),
                          Ab + (size_t)row * K + kb + lseg * 8);
            }
            if (lrow < 64)
                cpasync16(smem_u32(&Bs[nbuf][lrow][lseg * 8]),
                          Bb + (size_t)lrow * K + kb + lseg * 8);
            CP_COMMIT();
        }

#pragma unroll
        for (int ks = 0; ks < 2; ks++) {
            unsigned a[2][4], bb[4][2];
#pragma unroll
            for (int mf = 0; mf < 2; mf++) {
                int r = wm * 32 + mf * 16 + (lane & 15);
                int c = ks * 16 + (lane >> 4) * 8;
                ldm_x4(a[mf][0], a[mf][1], a[mf][2], a[mf][3],
                       smem_u32(&As[buf][r][c]));
            }
#pragma unroll
            for (int nh = 0; nh < 2; nh++) {
                int r = wn * 32 + nh * 16 + (lane >> 4) * 8 + (lane & 7);
                int c = ks * 16 + ((lane >> 3) & 1) * 8;
                unsigned r0, r1, r2, r3;
                ldm_x4(r0, r1, r2, r3, smem_u32(&Bs[buf][r][c]));
                bb[nh * 2][0] = r0; bb[nh * 2][1] = r1;
                bb[nh * 2 + 1][0] = r2; bb[nh * 2 + 1][1] = r3;
            }
#pragma unroll
            for (int mf = 0; mf < 2; mf++)
#pragma unroll
                for (int nf = 0; nf < 4; nf++)
                    mma_bf16(acc[mf][nf], a[mf], bb[nf][0], bb[nf][1]);
        }
    }

    int g = lane >> 2, t = lane & 3;
#pragma unroll
    for (int mf = 0; mf < 2; mf++)
#pragma unroll
        for (int nf = 0; nf < 4; nf++) {
            int col = blockIdx.x * 64 + wn * 32 + nf * 8 + 2 * t;
#pragma unroll
            for (int rr = 0; rr < 2; rr++) {
                int row = blockIdx.y * 128 + wm * 32 + mf * 16 + g + rr * 8;
                float v0 = acc[mf][nf][rr * 2 + 0];
                float v1 = acc[mf][nf][rr * 2 + 1];
                if (bias) { v0 += __ldg(&bias[col]); v1 += __ldg(&bias[col + 1]); }
                if (do_gelu) {
                    v0 = 0.5f * v0 * (1.f + erff(v0 * 0.70710678118f));
                    v1 = 0.5f * v1 * (1.f + erff(v1 * 0.70710678118f));
                }
                if (res) {
                    float2 rv = *(const float2*)(res + (size_t)row * N + col);
                    v0 += rv.x; v1 += rv.y;
                }
                if (Cf) {
                    float2 o; o.x = v0; o.y = v1;
                    *(float2*)(Cf + (size_t)row * N + col) = o;
                } else {
                    __nv_bfloat162 b2 = __floats2bfloat162_rn(v0, v1);
                    *(__nv_bfloat162*)(Cb + (size_t)row * N + col) = b2;
                }
            }
        }
}

// ---------------- all weight transposes fp32[K,N] -> bf16[N,K], one launch ---
#define WT0 442368
#define WT1 589824
#define WT2 663552
#define WT3 958464
#define WT4 1253376
#define WT5 1327104
__global__ __launch_bounds__(256) void wtrans_all(
    const float* __restrict__ w0, const float* __restrict__ w1,
    const float* __restrict__ w2, const float* __restrict__ w3,
    const float* __restrict__ w4, const float* __restrict__ w5)
{
    int i = blockIdx.x * 256 + threadIdx.x;
    if (i >= WT5) return;
    const float* s; __nv_bfloat16* d; int off, K;
    if      (i < WT0) { s = w0; d = g_wq;  off = 0;   K = 384; }
    else if (i < WT1) { s = w1; d = g_wp;  off = WT0; K = 384; }
    else if (i < WT2) { s = w2; d = g_w1d; off = WT1; K = 384; }
    else if (i < WT3) { s = w3; d = g_w1u; off = WT2; K = 192; }
    else if (i < WT4) { s = w4; d = g_w2d; off = WT3; K = 1536; }
    else              { s = w5; d = g_w2u; off = WT4; K = 192; }
    int j = i - off;
    int n = j / K, k = j - n * K;
    int N = (i < WT0) ? 1152 : (i < WT1) ? 384 : (i < WT2) ? 192 :
            (i < WT3) ? 1536 : (i < WT4) ? 192 : 384;
    d[j] = __float2bfloat16(s[(size_t)k * N + n]);
}

// ---------------- depthwise 3x3 conv (correlation, SAME) --------------------
__global__ __launch_bounds__(256) void dwconv_kernel(
    const float* __restrict__ pA, long strideA,
    const float* __restrict__ pB, long strideB,
    const float* __restrict__ w, const float* __restrict__ bias,
    float* __restrict__ out)
{
    int idx = blockIdx.x * 256 + threadIdx.x;
    if (idx >= Bsz * SPLIT * NTOK) return;
    int n = idx % NTOK;
    int c = (idx / NTOK) % SPLIT;
    int b = idx / (NTOK * SPLIT);
    int hh = n / WW, ww = n % WW;
    const float* a  = pA + (size_t)b * strideA + (size_t)c * NTOK;
    const float* bb = pB + (size_t)b * strideB + (size_t)c * NTOK;
    float acc = bias[c];
#pragma unroll
    for (int i = 0; i < 3; i++) {
        int ih = hh + i - 1;
        if (ih < 0 || ih >= HH) continue;
#pragma unroll
        for (int j = 0; j < 3; j++) {
            int iw = ww + j - 1;
            if (iw < 0 || iw >= WW) continue;
            int off = ih * WW + iw;
            acc += w[c * 9 + i * 3 + j] * (a[off] + bb[off]);
        }
    }
    out[idx] = acc;
}

// -------- fused assemble + LN1: NCHW sources -> bf16 token-major y16 --------
__global__ __launch_bounds__(256) void assemble_ln1(
    const float* __restrict__ x, const float* __restrict__ g,
    const float* __restrict__ bta)
{
    __shared__ float tile[384][33];
    int b = blockIdx.y, n0 = blockIdx.x * 32;
    int tid = threadIdx.x;

    // load 384 channels x 32 tokens (each warp: one channel row, coalesced)
    for (int i = tid; i < 384 * 32; i += 256) {
        int c = i >> 5, t = i & 31;
        const float* src;
        if (c < 128)      src = x    + ((size_t)b * CDIM  + c)        * NTOK;
        else if (c < 256) src = g_s1 + ((size_t)b * SPLIT + (c-128)) * NTOK;
        else              src = g_s2 + ((size_t)b * SPLIT + (c-256)) * NTOK;
        tile[c][t] = src[n0 + t];
    }
    __syncthreads();

    // per-token LN: 8 lanes per token
    int tok = tid >> 3, l8 = tid & 7;
    float s = 0.f, s2 = 0.f;
#pragma unroll 6
    for (int k = l8; k < 384; k += 8) {
        float v = tile[k][tok];
        s += v; s2 += v * v;
    }
#pragma unroll
    for (int o = 4; o > 0; o >>= 1) {
        s  += __shfl_xor_sync(0xFFFFFFFFu, s,  o);
        s2 += __shfl_xor_sync(0xFFFFFFFFu, s2, o);
    }
    float m  = s * (1.f / 384.f);
    float var = s2 * (1.f / 384.f) - m * m;
    float rs = rsqrtf(var + 1e-6f);

    // write 48 channels per lane, contiguous 96B -> 6x uint4, fully coalesced
    __nv_bfloat16* dst = g_y16 + ((size_t)(b * NTOK + n0 + tok)) * CDIM + l8 * 48;
#pragma unroll
    for (int j4 = 0; j4 < 6; j4++) {
        unsigned w[4];
#pragma unroll
        for (int q = 0; q < 4; q++) {
            int c = l8 * 48 + j4 * 8 + q * 2;
            float v0 = (tile[c][tok]     - m) * rs * __ldg(&g[c])     + __ldg(&bta[c]);
            float v1 = (tile[c + 1][tok] - m) * rs * __ldg(&g[c + 1]) + __ldg(&bta[c + 1]);
            __nv_bfloat162 b2 = __floats2bfloat162_rn(v0, v1);
            w[q] = *(unsigned*)&b2;
        }
        uint4 o; o.x = w[0]; o.y = w[1]; o.z = w[2]; o.w = w[3];
        ((uint4*)dst)[j4] = o;
    }
}

// ---------------- LayerNorm over C=384, bf16 output (LN2) -------------------
__global__ __launch_bounds__(128) void ln_kernel(
    const float* __restrict__ src, __nv_bfloat16* __restrict__ dst,
    const float* __restrict__ g, const float* __restrict__ bta)
{
    int tok = blockIdx.x;
    const float* r = src + (size_t)tok * CDIM;
    int tid = threadIdx.x;
    float v0 = r[tid], v1 = r[tid + 128], v2 = r[tid + 256];
    float s  = v0 + v1 + v2;
    float s2 = v0 * v0 + v1 * v1 + v2 * v2;
#pragma unroll
    for (int o = 16; o > 0; o >>= 1) {
        s  += __shfl_down_sync(0xFFFFFFFFu, s,  o);
        s2 += __shfl_down_sync(0xFFFFFFFFu, s2, o);
    }
    __shared__ float ss[4], ss2[4];
    int w = tid >> 5;
    if ((tid & 31) == 0) { ss[w] = s; ss2[w] = s2; }
    __syncthreads();
    if (tid == 0) {
        float a  = ss[0] + ss[1] + ss[2] + ss[3];
        float a2 = ss2[0] + ss2[1] + ss2[2] + ss2[3];
        float m  = a / CDIM;
        float var = a2 / CDIM - m * m;
        ss[0] = m; ss2[0] = rsqrtf(var + 1e-6f);
    }
    __syncthreads();
    float m = ss[0], rs = ss2[0];
    __nv_bfloat16* d = dst + (size_t)tok * CDIM;
    d[tid]       = __float2bfloat16((v0 - m) * rs * g[tid]       + bta[tid]);
    d[tid + 128] = __float2bfloat16((v1 - m) * rs * g[tid + 128] + bta[tid + 128]);
    d[tid + 256] = __float2bfloat16((v2 - m) * rs * g[tid + 256] + bta[tid + 256]);
}

// ---------------- XCA attention, kernel A: partial Gram + sumsq -------------
__global__ __launch_bounds__(256) void attn_gram()
{
    const __nv_bfloat16* qkv16 = (const __nv_bfloat16*)g_big;
    int s = blockIdx.x, h = blockIdx.y, b = blockIdx.z;
    __shared__ float q_s[48][66];
    __shared__ float k_s[48][66];
    int tid = threadIdx.x;
    int td = tid >> 4, te = tid & 15;

    ull acc2[3][3];
#pragma unroll
    for (int i = 0; i < 3; i++)
#pragma unroll
        for (int j = 0; j < 3; j++) acc2[i][j] = 0ULL;
    float qssl = 0.f, kssl = 0.f;

    for (int t = 0; t < 7; t++) {
        int n0 = (s * 7 + t) * 64;
        for (int i = tid; i < 48 * 64; i += 256) {
            int d = i % 48, nn = i / 48;
            size_t base = ((size_t)(b * NTOK + n0 + nn)) * 1152 + h * 48 + d;
            q_s[d][nn] = __bfloat162float(qkv16[base]);
            k_s[d][nn] = __bfloat162float(qkv16[base + 384]);
        }
        __syncthreads();
        if (tid < 48) {
            float tt = 0.f;
#pragma unroll 8
            for (int nn = 0; nn < 64; nn++) { float vv = q_s[tid][nn]; tt += vv * vv; }
            qssl += tt;
        } else if (tid >= 64 && tid < 112) {
            int d = tid - 64;
            float tt = 0.f;
#pragma unroll 8
            for (int nn = 0; nn < 64; nn++) { float vv = k_s[d][nn]; tt += vv * vv; }
            kssl += tt;
        }
#pragma unroll 4
        for (int nn2 = 0; nn2 < 32; nn2++) {
            ull q2[3], k2[3];
#pragma unroll
            for (int i = 0; i < 3; i++)
                q2[i] = *(const ull*)&q_s[td * 3 + i][2 * nn2];
#pragma unroll
            for (int j = 0; j < 3; j++)
                k2[j] = *(const ull*)&k_s[te * 3 + j][2 * nn2];
#pragma unroll
            for (int i = 0; i < 3; i++)
#pragma unroll
                for (int j = 0; j < 3; j++)
                    acc2[i][j] = fma2(q2[i], k2[j], acc2[i][j]);
        }
        __syncthreads();
    }
    int bh = b * 8 + h;
    size_t gbase = ((size_t)(s * 128 + bh)) * 2304;
#pragma unroll
    for (int i = 0; i < 3; i++)
#pragma unroll
        for (int j = 0; j < 3; j++) {
            float lo, hi;
            unpk(lo, hi, acc2[i][j]);
            g_gramP[gbase + (td * 3 + i) * 48 + te * 3 + j] = lo + hi;
        }
    if (tid < 48)                 g_qsqP[(size_t)(s * 128 + bh) * 48 + tid] = qssl;
    if (tid >= 64 && tid < 112)   g_ksqP[(size_t)(s * 128 + bh) * 48 + tid - 64] = kssl;
}

// ---------------- kernel B: reduce partials, softmax, pre-replicate ---------
__global__ __launch_bounds__(64) void attn_soft()
{
    int h = blockIdx.x, b = blockIdx.y;
    int bh = b * 8 + h;
    __shared__ float qn[48], kn[48];
    int tid = threadIdx.x;
    if (tid < 48) {
        float q = 0.f, k = 0.f;
#pragma unroll
        for (int s = 0; s < NSPL; s++) {
            q += g_qsqP[(size_t)(s * 128 + bh) * 48 + tid];
            k += g_ksqP[(size_t)(s * 128 + bh) * 48 + tid];
        }
        qn[tid] = fmaxf(sqrtf(q), 1e-12f);
        kn[tid] = fmaxf(sqrtf(k), 1e-12f);
    }
    __syncthreads();
    if (tid < 48) {
        int r = tid;
        float vals[48];
        float iq = 1.f / qn[r];
#pragma unroll 8
        for (int e = 0; e < 48; e++) {
            float gsum = 0.f;
#pragma unroll
            for (int s = 0; s < NSPL; s++)
                gsum += g_gramP[((size_t)(s * 128 + bh)) * 2304 + r * 48 + e];
            vals[e] = gsum * iq / kn[e];
        }
        float mx = -1e30f;
#pragma unroll 8
        for (int e = 0; e < 48; e++) mx = fmaxf(mx, vals[e]);
        float sm = 0.f;
#pragma unroll 8
        for (int e = 0; e < 48; e++) { vals[e] = expf(vals[e] - mx); sm += vals[e]; }
        float inv = 1.f / sm;
        float2* dst = g_attn2 + (size_t)bh * 2304 + r * 48;
#pragma unroll 8
        for (int e = 0; e < 48; e++) {
            float p = vals[e] * inv;
            dst[e] = make_float2(p, p);
        }
    }
}

// ---------------- kernel C: y = attn @ V, f32x2, 2 tokens/lane --------------
__global__ __launch_bounds__(256) void attn_apply()
{
    const __nv_bfloat16* qkv16 = (const __nv_bfloat16*)g_big;
    int s = blockIdx.x, h = blockIdx.y, b = blockIdx.z;
    __shared__ float2 a2s[2304];
    int tid = threadIdx.x, lane = tid & 31, wid = tid >> 5;
    const float2* gsrc = g_attn2 + (size_t)(b * 8 + h) * 2304;
    for (int i = tid; i < 2304; i += 256) a2s[i] = gsrc[i];
    __syncthreads();

    int wt = s * 8 + wid;
    if (wt >= 49) return;
    int tA = wt * 64 + lane, tB = tA + 32;

    const uint4* vpA = (const uint4*)(qkv16 + ((size_t)(b * NTOK + tA)) * 1152 + 768 + h * 48);
    const uint4* vpB = (const uint4*)(qkv16 + ((size_t)(b * NTOK + tB)) * 1152 + 768 + h * 48);
    ull v2[48];
#pragma unroll
    for (int i = 0; i < 6; i++) {
        uint4 ta = vpA[i], tb = vpB[i];
        unsigned wa[4] = { ta.x, ta.y, ta.z, ta.w };
        unsigned wb[4] = { tb.x, tb.y, tb.z, tb.w };
#pragma unroll
        for (int q = 0; q < 4; q++) {
            float2 fa = __bfloat1622float2(*(__nv_bfloat162*)&wa[q]);
            float2 fb = __bfloat1622float2(*(__nv_bfloat162*)&wb[q]);
            v2[i * 8 + q * 2 + 0] = pk(fa.x, fb.x);
            v2[i * 8 + q * 2 + 1] = pk(fa.y, fb.y);
        }
    }

#pragma unroll
    for (int half = 0; half < 2; half++) {
        float oA[24], oB[24];
#pragma unroll
        for (int d = 0; d < 24; d++) {
            int dd = half * 24 + d;
            ull acc = 0ULL;
            const longlong2* ap = (const longlong2*)&a2s[dd * 48];
#pragma unroll
            for (int e2 = 0; e2 < 24; e2++) {
                longlong2 av = ap[e2];
                acc = fma2((ull)av.x, v2[2 * e2], acc);
                acc = fma2((ull)av.y, v2[2 * e2 + 1], acc);
            }
            unpk(oA[d], oB[d], acc);
        }
        __nv_bfloat16* pA = g_att16 + ((size_t)(b * NTOK + tA)) * CDIM + h * 48 + half * 24;
        __nv_bfloat16* pB = g_att16 + ((size_t)(b * NTOK + tB)) * CDIM + h * 48 + half * 24;
        unsigned wA[12], wB[12];
#pragma unroll
        for (int j = 0; j < 12; j++) {
            __nv_bfloat162 xa = __floats2bfloat162_rn(oA[2 * j], oA[2 * j + 1]);
            __nv_bfloat162 xb = __floats2bfloat162_rn(oB[2 * j], oB[2 * j + 1]);
            wA[j] = *(unsigned*)&xa; wB[j] = *(unsigned*)&xb;
        }
#pragma unroll
        for (int j = 0; j < 3; j++) {
            uint4 oa; oa.x = wA[4*j]; oa.y = wA[4*j+1]; oa.z = wA[4*j+2]; oa.w = wA[4*j+3];
            uint4 ob; ob.x = wB[4*j]; ob.y = wB[4*j+1]; ob.z = wB[4*j+2]; ob.w = wB[4*j+3];
            ((uint4*)pA)[j] = oa;
            ((uint4*)pB)[j] = ob;
        }
    }
}

// ---------------------------------------------------------------------------
extern "C" void kernel_launch(void* const* d_in, const int* in_sizes, int n_in,
                              void* d_out, int out_size)
{
    const float* x       = (const float*)d_in[0];
    const float* dw_w0   = (const float*)d_in[1];
    const float* dw_b0   = (const float*)d_in[2];
    const float* dw_w1   = (const float*)d_in[3];
    const float* dw_b1   = (const float*)d_in[4];
    const float* ln1_g   = (const float*)d_in[5];
    const float* ln1_b   = (const float*)d_in[6];
    const float* qkv_w   = (const float*)d_in[7];
    const float* proj_w  = (const float*)d_in[8];
    const float* proj_b  = (const float*)d_in[9];
    const float* ln2_g   = (const float*)d_in[10];
    const float* ln2_b   = (const float*)d_in[11];
    const float* mlp1_dw = (const float*)d_in[12];
    const float* mlp1_uw = (const float*)d_in[13];
    const float* mlp1_ub = (const float*)d_in[14];
    const float* mlp2_dw = (const float*)d_in[15];
    const float* mlp2_uw = (const float*)d_in[16];
    const float* mlp2_ub = (const float*)d_in[17];
    float* out = (float*)d_out;

    float *big, *s1, *s2, *xf2;
    __nv_bfloat16 *y16, *att16, *t116, *t216, *h16;
    __nv_bfloat16 *wq, *wp, *w1d, *w1u, *w2d, *w2u;
    cudaGetSymbolAddress((void**)&big,  g_big);
    cudaGetSymbolAddress((void**)&s1,   g_s1);
    cudaGetSymbolAddress((void**)&s2,   g_s2);
    cudaGetSymbolAddress((void**)&xf2,  g_xf2);
    cudaGetSymbolAddress((void**)&y16,  g_y16);
    cudaGetSymbolAddress((void**)&att16,g_att16);
    cudaGetSymbolAddress((void**)&t116, g_t116);
    cudaGetSymbolAddress((void**)&t216, g_t216);
    cudaGetSymbolAddress((void**)&h16,  g_h16);
    cudaGetSymbolAddress((void**)&wq,   g_wq);
    cudaGetSymbolAddress((void**)&wp,   g_wp);
    cudaGetSymbolAddress((void**)&w1d,  g_w1d);
    cudaGetSymbolAddress((void**)&w1u,  g_w1u);
    cudaGetSymbolAddress((void**)&w2d,  g_w2d);
    cudaGetSymbolAddress((void**)&w2u,  g_w2u);
    __nv_bfloat16* qkv16 = (__nv_bfloat16*)big;

    wtrans_all<<<(WT5 + 255) / 256, 256>>>(qkv_w, proj_w, mlp1_dw, mlp1_uw,
                                           mlp2_dw, mlp2_uw);

    int nconv = Bsz * SPLIT * NTOK;
    int cblk = (nconv + 255) / 256;

    dwconv_kernel<<<cblk, 256>>>(x, (long)CDIM * NTOK,
                                 x + (size_t)SPLIT * NTOK, (long)CDIM * NTOK,
                                 dw_w0, dw_b0, s1);
    dwconv_kernel<<<cblk, 256>>>(s1, (long)SPLIT * NTOK,
                                 x + (size_t)2 * SPLIT * NTOK, (long)CDIM * NTOK,
                                 dw_w1, dw_b1, s2);

    // fused assemble + LN1 (reads x/s1/s2 NCHW, writes bf16 token-major y16)
    assemble_ln1<<<dim3(98, Bsz), 256>>>(x, ln1_g, ln1_b);

    // qkv = y @ qkv_w (bf16 out into g_big alias)
    bgemm128<<<dim3(1152/128, TOKS/128), 256>>>(y16, wq, nullptr, qkv16,
                                                TOKS, 1152, 384, nullptr, nullptr, 0);

    // attention: gram partials -> softmax -> apply
    attn_gram<<<dim3(NSPL, NHEAD, Bsz), 256>>>();
    attn_soft<<<dim3(NHEAD, Bsz), 64>>>();
    attn_apply<<<dim3(NSPL, NHEAD, Bsz), 256>>>();

    // xf2 = x_flat + att @ proj_w + proj_b  (residual read from NCHW sources)
    bgemm128_resnchw<<<dim3(384/128, TOKS/128), 256>>>(att16, wp, xf2,
                                                       TOKS, 384, 384, proj_b,
                                                       x, s1, s2);

    ln_kernel<<<TOKS, 128>>>(xf2, y16, ln2_g, ln2_b);

    bgemm<<<dim3(192/64, TOKS/128), 256>>>(y16, w1d, nullptr, t116,
                                           TOKS, 192, 384, nullptr, nullptr, 0);
    bgemm128<<<dim3(1536/128, TOKS/128), 256>>>(t116, w1u, nullptr, h16,
                                                TOKS, 1536, 192, mlp1_ub, nullptr, 1);
    bgemm<<<dim3(192/64, TOKS/128), 256>>>(h16, w2d, nullptr, t216,
                                           TOKS, 192, 1536, nullptr, nullptr, 0);
    // final: out(NCHW) = xf2 + t2 @ mlp2_uw + b, fused transpose
    bgemm128_nchw<<<dim3(384/128, TOKS/128), 256>>>(t216, w2u, out,
                                                    TOKS, 384, 192, mlp2_ub, xf2);

    (void)in_sizes; (void)n_in; (void)out_size;
}

// round 15
// speedup vs baseline: 1.0545x; 1.0545x over previous
#include <cuda_runtime.h>
#include <cuda_bf16.h>
#include <math.h>

#define Bsz   16
#define CDIM  384
#define HH    56
#define WW    56
#define NTOK  3136          // 56*56
#define TOKS  (Bsz*NTOK)    // 50176
#define NHEAD 8
#define SPLIT 128
#define HID   1536
#define RR    192
#define NSPL  7             // attention token splits (49 tiles of 64 = 7x7)

typedef unsigned long long ull;

// ---------------- scratch (device globals; no allocations allowed) ----------
__device__ float g_big[(size_t)TOKS*1152];     // bf16 qkv alias lives here
__device__ float g_s1 [(size_t)Bsz*SPLIT*NTOK];
__device__ float g_s2 [(size_t)Bsz*SPLIT*NTOK];
__device__ float g_xf [(size_t)TOKS*CDIM];
__device__ float g_xf2[(size_t)TOKS*CDIM];
__device__ __nv_bfloat16 g_y16 [(size_t)TOKS*CDIM];
__device__ __nv_bfloat16 g_att16[(size_t)TOKS*CDIM];
__device__ __nv_bfloat16 g_t116[(size_t)TOKS*RR];
__device__ __nv_bfloat16 g_t216[(size_t)TOKS*RR];
__device__ __nv_bfloat16 g_h16 [(size_t)TOKS*HID];
// attention staging
__device__ float  g_gramP[(size_t)NSPL*128*2304];
__device__ float  g_qsqP [(size_t)NSPL*128*48];
__device__ float  g_ksqP [(size_t)NSPL*128*48];
__device__ float2 g_attn2[(size_t)128*2304];
// transposed bf16 weights, [N, K] K-major rows
__device__ __nv_bfloat16 g_wq [1152*384];
__device__ __nv_bfloat16 g_wp [384*384];
__device__ __nv_bfloat16 g_w1d[192*384];
__device__ __nv_bfloat16 g_w1u[1536*192];
__device__ __nv_bfloat16 g_w2d[192*1536];
__device__ __nv_bfloat16 g_w2u[384*192];

// ---------------- helpers ----------------------------------------------------
__device__ __forceinline__ unsigned smem_u32(const void* p) {
    unsigned a;
    asm("{ .reg .u64 t; cvta.to.shared.u64 t, %1; cvt.u32.u64 %0, t; }"
        : "=r"(a) : "l"(p));
    return a;
}
__device__ __forceinline__ void cpasync16(unsigned dst, const void* src) {
    asm volatile("cp.async.cg.shared.global [%0], [%1], 16;" :: "r"(dst), "l"(src));
}
#define CP_COMMIT() asm volatile("cp.async.commit_group;" ::: "memory")
__device__ __forceinline__ void ldm_x4(unsigned& r0, unsigned& r1, unsigned& r2,
                                       unsigned& r3, unsigned addr) {
    asm volatile("ldmatrix.sync.aligned.m8n8.x4.shared.b16 {%0,%1,%2,%3}, [%4];"
                 : "=r"(r0), "=r"(r1), "=r"(r2), "=r"(r3) : "r"(addr));
}
__device__ __forceinline__ void mma_bf16(float* d, const unsigned* a,
                                         unsigned b0, unsigned b1) {
    asm volatile(
        "mma.sync.aligned.m16n8k16.row.col.f32.bf16.bf16.f32 "
        "{%0,%1,%2,%3}, {%4,%5,%6,%7}, {%8,%9}, {%0,%1,%2,%3};\n"
        : "+f"(d[0]), "+f"(d[1]), "+f"(d[2]), "+f"(d[3])
        : "r"(a[0]), "r"(a[1]), "r"(a[2]), "r"(a[3]), "r"(b0), "r"(b1));
}
// packed f32x2 (sm_100+ baseline PTX, not arch-'a'-gated)
__device__ __forceinline__ ull fma2(ull a, ull b, ull c) {
    ull d;
    asm("fma.rn.f32x2 %0, %1, %2, %3;" : "=l"(d) : "l"(a), "l"(b), "l"(c));
    return d;
}
__device__ __forceinline__ ull pk(float lo, float hi) {
    ull r;
    asm("mov.b64 %0, {%1, %2};" : "=l"(r) : "f"(lo), "f"(hi));
    return r;
}
__device__ __forceinline__ void unpk(float& lo, float& hi, ull v) {
    asm("mov.b64 {%0, %1}, %2;" : "=f"(lo), "=f"(hi) : "l"(v));
}

#define ASTR 40   // padded row stride (bf16): 32 data + 8 pad -> conflict-free ldmatrix

// ============ bf16 GEMM, 128x128 tile (N % 128 == 0), 3-stage pipeline =======
__global__ __launch_bounds__(256) void bgemm128(
    const __nv_bfloat16* __restrict__ A, const __nv_bfloat16* __restrict__ Bw,
    float* __restrict__ Cf, __nv_bfloat16* __restrict__ Cb,
    int M, int N, int K,
    const float* __restrict__ bias, const float* __restrict__ res, int do_gelu)
{
    __shared__ __align__(16) __nv_bfloat16 As[3][128][ASTR];
    __shared__ __align__(16) __nv_bfloat16 Bs[3][128][ASTR];
    int tid = threadIdx.x, lane = tid & 31, wid = tid >> 5;
    int wm = wid & 1, wn = wid >> 1;
    const __nv_bfloat16* Ab = A  + (size_t)blockIdx.y * 128 * K;
    const __nv_bfloat16* Bb = Bw + (size_t)blockIdx.x * 128 * K;

    float acc[4][4][4];
#pragma unroll
    for (int mf = 0; mf < 4; mf++)
#pragma unroll
        for (int nf = 0; nf < 4; nf++)
#pragma unroll
            for (int i = 0; i < 4; i++) acc[mf][nf][i] = 0.f;

    int nk = K >> 5;
    int lrow = tid >> 2, lseg = tid & 3;

#pragma unroll
    for (int pc = 0; pc < 2; pc++) {
        long kb = (long)pc * 32;
#pragma unroll
        for (int i = 0; i < 2; i++) {
            int row = lrow + i * 64;
            cpasync16(smem_u32(&As[pc][row][lseg * 8]), Ab + (size_t)row * K + kb + lseg * 8);
            cpasync16(smem_u32(&Bs[pc][row][lseg * 8]), Bb + (size_t)row * K + kb + lseg * 8);
        }
        CP_COMMIT();
    }

    for (int kc = 0; kc < nk; kc++) {
        int buf = kc % 3;
        if (kc + 1 < nk) asm volatile("cp.async.wait_group 1;" ::: "memory");
        else             asm volatile("cp.async.wait_group 0;" ::: "memory");
        __syncthreads();
        if (kc + 2 < nk) {
            int nbuf = (kc + 2) % 3;
            long kb = (long)(kc + 2) * 32;
#pragma unroll
            for (int i = 0; i < 2; i++) {
                int row = lrow + i * 64;
                cpasync16(smem_u32(&As[nbuf][row][lseg * 8]),
                          Ab + (size_t)row * K + kb + lseg * 8);
                cpasync16(smem_u32(&Bs[nbuf][row][lseg * 8]),
                          Bb + (size_t)row * K + kb + lseg * 8);
            }
            CP_COMMIT();
        }

#pragma unroll
        for (int ks = 0; ks < 2; ks++) {
            unsigned a[4][4], bb[4][2];
#pragma unroll
            for (int mf = 0; mf < 4; mf++) {
                int r = wm * 64 + mf * 16 + (lane & 15);
                int c = ks * 16 + (lane >> 4) * 8;
                ldm_x4(a[mf][0], a[mf][1], a[mf][2], a[mf][3],
                       smem_u32(&As[buf][r][c]));
            }
#pragma unroll
            for (int nh = 0; nh < 2; nh++) {
                int r = wn * 32 + nh * 16 + (lane >> 4) * 8 + (lane & 7);
                int c = ks * 16 + ((lane >> 3) & 1) * 8;
                unsigned r0, r1, r2, r3;
                ldm_x4(r0, r1, r2, r3, smem_u32(&Bs[buf][r][c]));
                bb[nh * 2][0] = r0; bb[nh * 2][1] = r1;
                bb[nh * 2 + 1][0] = r2; bb[nh * 2 + 1][1] = r3;
            }
#pragma unroll
            for (int mf = 0; mf < 4; mf++)
#pragma unroll
                for (int nf = 0; nf < 4; nf++)
                    mma_bf16(acc[mf][nf], a[mf], bb[nf][0], bb[nf][1]);
        }
    }

    int g = lane >> 2, t = lane & 3;
#pragma unroll
    for (int mf = 0; mf < 4; mf++)
#pragma unroll
        for (int nf = 0; nf < 4; nf++) {
            int col = blockIdx.x * 128 + wn * 32 + nf * 8 + 2 * t;
#pragma unroll
            for (int rr = 0; rr < 2; rr++) {
                int row = blockIdx.y * 128 + wm * 64 + mf * 16 + g + rr * 8;
                float v0 = acc[mf][nf][rr * 2 + 0];
                float v1 = acc[mf][nf][rr * 2 + 1];
                if (bias) { v0 += __ldg(&bias[col]); v1 += __ldg(&bias[col + 1]); }
                if (do_gelu) {
                    v0 = 0.5f * v0 * (1.f + erff(v0 * 0.70710678118f));
                    v1 = 0.5f * v1 * (1.f + erff(v1 * 0.70710678118f));
                }
                if (res) {
                    float2 rv = *(const float2*)(res + (size_t)row * N + col);
                    v0 += rv.x; v1 += rv.y;
                }
                if (Cf) {
                    float2 o; o.x = v0; o.y = v1;
                    *(float2*)(Cf + (size_t)row * N + col) = o;
                } else {
                    __nv_bfloat162 b2 = __floats2bfloat162_rn(v0, v1);
                    *(__nv_bfloat162*)(Cb + (size_t)row * N + col) = b2;
                }
            }
        }
}

// ============ proj GEMM: 128x128 tile, residual read from NCHW sources ======
__global__ __launch_bounds__(256) void bgemm128_resnchw(
    const __nv_bfloat16* __restrict__ A, const __nv_bfloat16* __restrict__ Bw,
    float* __restrict__ Cf, int M, int N, int K,
    const float* __restrict__ bias,
    const float* __restrict__ rx, const float* __restrict__ rs1,
    const float* __restrict__ rs2)
{
    __shared__ __align__(16) __nv_bfloat16 As[3][128][ASTR];
    __shared__ __align__(16) __nv_bfloat16 Bs[3][128][ASTR];
    int tid = threadIdx.x, lane = tid & 31, wid = tid >> 5;
    int wm = wid & 1, wn = wid >> 1;
    const __nv_bfloat16* Ab = A  + (size_t)blockIdx.y * 128 * K;
    const __nv_bfloat16* Bb = Bw + (size_t)blockIdx.x * 128 * K;

    float acc[4][4][4];
#pragma unroll
    for (int mf = 0; mf < 4; mf++)
#pragma unroll
        for (int nf = 0; nf < 4; nf++)
#pragma unroll
            for (int i = 0; i < 4; i++) acc[mf][nf][i] = 0.f;

    int nk = K >> 5;
    int lrow = tid >> 2, lseg = tid & 3;

#pragma unroll
    for (int pc = 0; pc < 2; pc++) {
        long kb = (long)pc * 32;
#pragma unroll
        for (int i = 0; i < 2; i++) {
            int row = lrow + i * 64;
            cpasync16(smem_u32(&As[pc][row][lseg * 8]), Ab + (size_t)row * K + kb + lseg * 8);
            cpasync16(smem_u32(&Bs[pc][row][lseg * 8]), Bb + (size_t)row * K + kb + lseg * 8);
        }
        CP_COMMIT();
    }

    for (int kc = 0; kc < nk; kc++) {
        int buf = kc % 3;
        if (kc + 1 < nk) asm volatile("cp.async.wait_group 1;" ::: "memory");
        else             asm volatile("cp.async.wait_group 0;" ::: "memory");
        __syncthreads();
        if (kc + 2 < nk) {
            int nbuf = (kc + 2) % 3;
            long kb = (long)(kc + 2) * 32;
#pragma unroll
            for (int i = 0; i < 2; i++) {
                int row = lrow + i * 64;
                cpasync16(smem_u32(&As[nbuf][row][lseg * 8]),
                          Ab + (size_t)row * K + kb + lseg * 8);
                cpasync16(smem_u32(&Bs[nbuf][row][lseg * 8]),
                          Bb + (size_t)row * K + kb + lseg * 8);
            }
            CP_COMMIT();
        }

#pragma unroll
        for (int ks = 0; ks < 2; ks++) {
            unsigned a[4][4], bb[4][2];
#pragma unroll
            for (int mf = 0; mf < 4; mf++) {
                int r = wm * 64 + mf * 16 + (lane & 15);
                int c = ks * 16 + (lane >> 4) * 8;
                ldm_x4(a[mf][0], a[mf][1], a[mf][2], a[mf][3],
                       smem_u32(&As[buf][r][c]));
            }
#pragma unroll
            for (int nh = 0; nh < 2; nh++) {
                int r = wn * 32 + nh * 16 + (lane >> 4) * 8 + (lane & 7);
                int c = ks * 16 + ((lane >> 3) & 1) * 8;
                unsigned r0, r1, r2, r3;
                ldm_x4(r0, r1, r2, r3, smem_u32(&Bs[buf][r][c]));
                bb[nh * 2][0] = r0; bb[nh * 2][1] = r1;
                bb[nh * 2 + 1][0] = r2; bb[nh * 2 + 1][1] = r3;
            }
#pragma unroll
            for (int mf = 0; mf < 4; mf++)
#pragma unroll
                for (int nf = 0; nf < 4; nf++)
                    mma_bf16(acc[mf][nf], a[mf], bb[nf][0], bb[nf][1]);
        }
    }

    int g = lane >> 2, t = lane & 3;
#pragma unroll
    for (int mf = 0; mf < 4; mf++)
#pragma unroll
        for (int nf = 0; nf < 4; nf++) {
            int col = blockIdx.x * 128 + wn * 32 + nf * 8 + 2 * t;
            float b0 = __ldg(&bias[col]), b1 = __ldg(&bias[col + 1]);
#pragma unroll
            for (int rr = 0; rr < 2; rr++) {
                int row = blockIdx.y * 128 + wm * 64 + mf * 16 + g + rr * 8;
                int b2 = row / NTOK, n = row - b2 * NTOK;
                const float* src;
                if (col < 128)      src = rx  + ((size_t)b2 * CDIM  + col)        * NTOK + n;
                else if (col < 256) src = rs1 + ((size_t)b2 * SPLIT + (col-128)) * NTOK + n;
                else                src = rs2 + ((size_t)b2 * SPLIT + (col-256)) * NTOK + n;
                float v0 = acc[mf][nf][rr * 2 + 0] + b0 + src[0];
                float v1 = acc[mf][nf][rr * 2 + 1] + b1 + src[NTOK];
                float2 o; o.x = v0; o.y = v1;
                *(float2*)(Cf + (size_t)row * N + col) = o;
            }
        }
}

// ============ final GEMM: 128x128 tile, N=384, writes NCHW out directly ======
__global__ __launch_bounds__(256) void bgemm128_nchw(
    const __nv_bfloat16* __restrict__ A, const __nv_bfloat16* __restrict__ Bw,
    float* __restrict__ out, int M, int N, int K,
    const float* __restrict__ bias, const float* __restrict__ res)
{
    __shared__ __align__(16) __nv_bfloat16 As[3][128][ASTR];
    __shared__ __align__(16) __nv_bfloat16 Bs[3][128][ASTR];
    __shared__ float tbuf[32][132];
    int tid = threadIdx.x, lane = tid & 31, wid = tid >> 5;
    int wm = wid & 1, wn = wid >> 1;
    const __nv_bfloat16* Ab = A  + (size_t)blockIdx.y * 128 * K;
    const __nv_bfloat16* Bb = Bw + (size_t)blockIdx.x * 128 * K;

    float acc[4][4][4];
#pragma unroll
    for (int mf = 0; mf < 4; mf++)
#pragma unroll
        for (int nf = 0; nf < 4; nf++)
#pragma unroll
            for (int i = 0; i < 4; i++) acc[mf][nf][i] = 0.f;

    int nk = K >> 5;
    int lrow = tid >> 2, lseg = tid & 3;

#pragma unroll
    for (int pc = 0; pc < 2; pc++) {
        long kb = (long)pc * 32;
#pragma unroll
        for (int i = 0; i < 2; i++) {
            int row = lrow + i * 64;
            cpasync16(smem_u32(&As[pc][row][lseg * 8]), Ab + (size_t)row * K + kb + lseg * 8);
            cpasync16(smem_u32(&Bs[pc][row][lseg * 8]), Bb + (size_t)row * K + kb + lseg * 8);
        }
        CP_COMMIT();
    }

    for (int kc = 0; kc < nk; kc++) {
        int buf = kc % 3;
        if (kc + 1 < nk) asm volatile("cp.async.wait_group 1;" ::: "memory");
        else             asm volatile("cp.async.wait_group 0;" ::: "memory");
        __syncthreads();
        if (kc + 2 < nk) {
            int nbuf = (kc + 2) % 3;
            long kb = (long)(kc + 2) * 32;
#pragma unroll
            for (int i = 0; i < 2; i++) {
                int row = lrow + i * 64;
                cpasync16(smem_u32(&As[nbuf][row][lseg * 8]),
                          Ab + (size_t)row * K + kb + lseg * 8);
                cpasync16(smem_u32(&Bs[nbuf][row][lseg * 8]),
                          Bb + (size_t)row * K + kb + lseg * 8);
            }
            CP_COMMIT();
        }

#pragma unroll
        for (int ks = 0; ks < 2; ks++) {
            unsigned a[4][4], bb[4][2];
#pragma unroll
            for (int mf = 0; mf < 4; mf++) {
                int r = wm * 64 + mf * 16 + (lane & 15);
                int c = ks * 16 + (lane >> 4) * 8;
                ldm_x4(a[mf][0], a[mf][1], a[mf][2], a[mf][3],
                       smem_u32(&As[buf][r][c]));
            }
#pragma unroll
            for (int nh = 0; nh < 2; nh++) {
                int r = wn * 32 + nh * 16 + (lane >> 4) * 8 + (lane & 7);
                int c = ks * 16 + ((lane >> 3) & 1) * 8;
                unsigned r0, r1, r2, r3;
                ldm_x4(r0, r1, r2, r3, smem_u32(&Bs[buf][r][c]));
                bb[nh * 2][0] = r0; bb[nh * 2][1] = r1;
                bb[nh * 2 + 1][0] = r2; bb[nh * 2 + 1][1] = r3;
            }
#pragma unroll
            for (int mf = 0; mf < 4; mf++)
#pragma unroll
                for (int nf = 0; nf < 4; nf++)
                    mma_bf16(acc[mf][nf], a[mf], bb[nf][0], bb[nf][1]);
        }
    }

    // epilogue: bias + residual, then transpose through smem, write NCHW
    int g = lane >> 2, t = lane & 3;
    __syncthreads();
#pragma unroll
    for (int p = 0; p < 4; p++) {
        if (wn == p) {
#pragma unroll
            for (int mf = 0; mf < 4; mf++)
#pragma unroll
                for (int nf = 0; nf < 4; nf++) {
                    int lcol = nf * 8 + 2 * t;
                    int col = blockIdx.x * 128 + p * 32 + lcol;
#pragma unroll
                    for (int rr = 0; rr < 2; rr++) {
                        int lrow2 = wm * 64 + mf * 16 + g + rr * 8;
                        int grow = blockIdx.y * 128 + lrow2;
                        float v0 = acc[mf][nf][rr * 2 + 0] + __ldg(&bias[col]);
                        float v1 = acc[mf][nf][rr * 2 + 1] + __ldg(&bias[col + 1]);
                        float2 rv = *(const float2*)(res + (size_t)grow * N + col);
                        v0 += rv.x; v1 += rv.y;
                        tbuf[lcol][lrow2] = v0;
                        tbuf[lcol + 1][lrow2] = v1;
                    }
                }
        }
        __syncthreads();
#pragma unroll
        for (int q = 0; q < 16; q++) {
            int lin = tid + q * 256;
            int ch = lin >> 7, row = lin & 127;
            int tok = blockIdx.y * 128 + row;
            int bb2 = tok / NTOK, n = tok - bb2 * NTOK;
            out[((size_t)bb2 * CDIM + blockIdx.x * 128 + p * 32 + ch) * NTOK + n] =
                tbuf[ch][row];
        }
        __syncthreads();
    }
}

// ============ bf16 GEMM, 128x64 tile (for N = 192), 3-stage pipeline =========
__global__ __launch_bounds__(256) void bgemm(
    const __nv_bfloat16* __restrict__ A, const __nv_bfloat16* __restrict__ Bw,
    float* __restrict__ Cf, __nv_bfloat16* __restrict__ Cb,
    int M, int N, int K,
    const float* __restrict__ bias, const float* __restrict__ res, int do_gelu)
{
    __shared__ __align__(16) __nv_bfloat16 As[3][128][ASTR];
    __shared__ __align__(16) __nv_bfloat16 Bs[3][64][ASTR];
    int tid = threadIdx.x, lane = tid & 31, wid = tid >> 5;
    int wm = wid & 3, wn = wid >> 2;
    const __nv_bfloat16* Ab = A  + (size_t)blockIdx.y * 128 * K;
    const __nv_bfloat16* Bb = Bw + (size_t)blockIdx.x * 64 * K;

    float acc[2][4][4];
#pragma unroll
    for (int mf = 0; mf < 2; mf++)
#pragma unroll
        for (int nf = 0; nf < 4; nf++)
#pragma unroll
            for (int i = 0; i < 4; i++) acc[mf][nf][i] = 0.f;

    int nk = K >> 5;
    int lrow = tid >> 2, lseg = tid & 3;

#pragma unroll
    for (int pc = 0; pc < 2; pc++) {
        long kb = (long)pc * 32;
#pragma unroll
        for (int i = 0; i < 2; i++) {
            int row = lrow + i * 64;
            cpasync16(smem_u32(&As[pc][row][lseg * 8]),
                      Ab + (size_t)row * K + kb + lseg * 8);
        }
        if (lrow < 64)
            cpasync16(smem_u32(&Bs[pc][lrow][lseg * 8]),
                      Bb + (size_t)lrow * K + kb + lseg * 8);
        CP_COMMIT();
    }

    for (int kc = 0; kc < nk; kc++) {
        int buf = kc % 3;
        if (kc + 1 < nk) asm volatile("cp.async.wait_group 1;" ::: "memory");
        else             asm volatile("cp.async.wait_group 0;" ::: "memory");
        __syncthreads();
        if (kc + 2 < nk) {
            int nbuf = (kc + 2) % 3;
            long kb = (long)(kc + 2) * 32;
#pragma unroll
            for (int i = 0; i < 2; i++) {
                int row = lrow + i * 64;
                cpasync16(smem_u32(&As[nbuf][row][lseg * 8]),
                          Ab + (size_t)row * K + kb + lseg * 8);
            }
            if (lrow < 64)
                cpasync16(smem_u32(&Bs[nbuf][lrow][lseg * 8]),
                          Bb + (size_t)lrow * K + kb + lseg * 8);
            CP_COMMIT();
        }

#pragma unroll
        for (int ks = 0; ks < 2; ks++) {
            unsigned a[2][4], bb[4][2];
#pragma unroll
            for (int mf = 0; mf < 2; mf++) {
                int r = wm * 32 + mf * 16 + (lane & 15);
                int c = ks * 16 + (lane >> 4) * 8;
                ldm_x4(a[mf][0], a[mf][1], a[mf][2], a[mf][3],
                       smem_u32(&As[buf][r][c]));
            }
#pragma unroll
            for (int nh = 0; nh < 2; nh++) {
                int r = wn * 32 + nh * 16 + (lane >> 4) * 8 + (lane & 7);
                int c = ks * 16 + ((lane >> 3) & 1) * 8;
                unsigned r0, r1, r2, r3;
                ldm_x4(r0, r1, r2, r3, smem_u32(&Bs[buf][r][c]));
                bb[nh * 2][0] = r0; bb[nh * 2][1] = r1;
                bb[nh * 2 + 1][0] = r2; bb[nh * 2 + 1][1] = r3;
            }
#pragma unroll
            for (int mf = 0; mf < 2; mf++)
#pragma unroll
                for (int nf = 0; nf < 4; nf++)
                    mma_bf16(acc[mf][nf], a[mf], bb[nf][0], bb[nf][1]);
        }
    }

    int g = lane >> 2, t = lane & 3;
#pragma unroll
    for (int mf = 0; mf < 2; mf++)
#pragma unroll
        for (int nf = 0; nf < 4; nf++) {
            int col = blockIdx.x * 64 + wn * 32 + nf * 8 + 2 * t;
#pragma unroll
            for (int rr = 0; rr < 2; rr++) {
                int row = blockIdx.y * 128 + wm * 32 + mf * 16 + g + rr * 8;
                float v0 = acc[mf][nf][rr * 2 + 0];
                float v1 = acc[mf][nf][rr * 2 + 1];
                if (bias) { v0 += __ldg(&bias[col]); v1 += __ldg(&bias[col + 1]); }
                if (do_gelu) {
                    v0 = 0.5f * v0 * (1.f + erff(v0 * 0.70710678118f));
                    v1 = 0.5f * v1 * (1.f + erff(v1 * 0.70710678118f));
                }
                if (res) {
                    float2 rv = *(const float2*)(res + (size_t)row * N + col);
                    v0 += rv.x; v1 += rv.y;
                }
                if (Cf) {
                    float2 o; o.x = v0; o.y = v1;
                    *(float2*)(Cf + (size_t)row * N + col) = o;
                } else {
                    __nv_bfloat162 b2 = __floats2bfloat162_rn(v0, v1);
                    *(__nv_bfloat162*)(Cb + (size_t)row * N + col) = b2;
                }
            }
        }
}

// ---------------- all weight transposes fp32[K,N] -> bf16[N,K], one launch ---
#define WT0 442368
#define WT1 589824
#define WT2 663552
#define WT3 958464
#define WT4 1253376
#define WT5 1327104
__global__ __launch_bounds__(256) void wtrans_all(
    const float* __restrict__ w0, const float* __restrict__ w1,
    const float* __restrict__ w2, const float* __restrict__ w3,
    const float* __restrict__ w4, const float* __restrict__ w5)
{
    int i = blockIdx.x * 256 + threadIdx.x;
    if (i >= WT5) return;
    const float* s; __nv_bfloat16* d; int off, K;
    if      (i < WT0) { s = w0; d = g_wq;  off = 0;   K = 384; }
    else if (i < WT1) { s = w1; d = g_wp;  off = WT0; K = 384; }
    else if (i < WT2) { s = w2; d = g_w1d; off = WT1; K = 384; }
    else if (i < WT3) { s = w3; d = g_w1u; off = WT2; K = 192; }
    else if (i < WT4) { s = w4; d = g_w2d; off = WT3; K = 1536; }
    else              { s = w5; d = g_w2u; off = WT4; K = 192; }
    int j = i - off;
    int n = j / K, k = j - n * K;
    int N = (i < WT0) ? 1152 : (i < WT1) ? 384 : (i < WT2) ? 192 :
            (i < WT3) ? 1536 : (i < WT4) ? 192 : 384;
    d[j] = __float2bfloat16(s[(size_t)k * N + n]);
}

// ---------------- depthwise 3x3 conv (correlation, SAME) --------------------
__global__ __launch_bounds__(256) void dwconv_kernel(
    const float* __restrict__ pA, long strideA,
    const float* __restrict__ pB, long strideB,
    const float* __restrict__ w, const float* __restrict__ bias,
    float* __restrict__ out)
{
    int idx = blockIdx.x * 256 + threadIdx.x;
    if (idx >= Bsz * SPLIT * NTOK) return;
    int n = idx % NTOK;
    int c = (idx / NTOK) % SPLIT;
    int b = idx / (NTOK * SPLIT);
    int hh = n / WW, ww = n % WW;
    const float* a  = pA + (size_t)b * strideA + (size_t)c * NTOK;
    const float* bb = pB + (size_t)b * strideB + (size_t)c * NTOK;
    float acc = bias[c];
#pragma unroll
    for (int i = 0; i < 3; i++) {
        int ih = hh + i - 1;
        if (ih < 0 || ih >= HH) continue;
#pragma unroll
        for (int j = 0; j < 3; j++) {
            int iw = ww + j - 1;
            if (iw < 0 || iw >= WW) continue;
            int off = ih * WW + iw;
            acc += w[c * 9 + i * 3 + j] * (a[off] + bb[off]);
        }
    }
    out[idx] = acc;
}

// ------------- assemble token-major x_flat from s0|s1|s2 (tiled transpose) --
__global__ __launch_bounds__(256) void assemble_kernel(const float* __restrict__ x)
{
    __shared__ float tile[32][33];
    int b = blockIdx.z, c0 = blockIdx.y * 32, n0 = blockIdx.x * 32;
    int tx = threadIdx.x, ty = threadIdx.y;
    const float* src;
    if (c0 < 128)      src = x    + ((size_t)b * CDIM  + c0)        * NTOK;
    else if (c0 < 256) src = g_s1 + ((size_t)b * SPLIT + (c0-128)) * NTOK;
    else               src = g_s2 + ((size_t)b * SPLIT + (c0-256)) * NTOK;
#pragma unroll
    for (int r = 0; r < 4; r++)
        tile[ty + r * 8][tx] = src[(size_t)(ty + r * 8) * NTOK + n0 + tx];
    __syncthreads();
#pragma unroll
    for (int r = 0; r < 4; r++)
        g_xf[((size_t)b * NTOK + n0 + ty + r * 8) * CDIM + c0 + tx] = tile[tx][ty + r * 8];
}

// ---------------- LayerNorm, warp-per-token, bf16 output --------------------
__global__ __launch_bounds__(256) void ln_warp(
    const float* __restrict__ src, __nv_bfloat16* __restrict__ dst,
    const float* __restrict__ g, const float* __restrict__ bta)
{
    int w = threadIdx.x >> 5, lane = threadIdx.x & 31;
    int tok = blockIdx.x * 8 + w;
    const float4* r = (const float4*)(src + (size_t)tok * CDIM);
    float v[12];
    float s = 0.f, s2 = 0.f;
#pragma unroll
    for (int k = 0; k < 3; k++) {
        float4 t = r[k * 32 + lane];
        v[k * 4 + 0] = t.x; v[k * 4 + 1] = t.y; v[k * 4 + 2] = t.z; v[k * 4 + 3] = t.w;
        s  += t.x + t.y + t.z + t.w;
        s2 += t.x * t.x + t.y * t.y + t.z * t.z + t.w * t.w;
    }
#pragma unroll
    for (int o = 16; o > 0; o >>= 1) {
        s  += __shfl_xor_sync(0xFFFFFFFFu, s,  o);
        s2 += __shfl_xor_sync(0xFFFFFFFFu, s2, o);
    }
    float m  = s * (1.f / CDIM);
    float var = s2 * (1.f / CDIM) - m * m;
    float rs = rsqrtf(var + 1e-6f);
    __nv_bfloat16* d = dst + (size_t)tok * CDIM;
#pragma unroll
    for (int k = 0; k < 3; k++) {
        int c = k * 128 + lane * 4;
        float4 gg = *(const float4*)(g + c);
        float4 bb = *(const float4*)(bta + c);
        float o0 = (v[k*4+0] - m) * rs * gg.x + bb.x;
        float o1 = (v[k*4+1] - m) * rs * gg.y + bb.y;
        float o2 = (v[k*4+2] - m) * rs * gg.z + bb.z;
        float o3 = (v[k*4+3] - m) * rs * gg.w + bb.w;
        __nv_bfloat162 p0 = __floats2bfloat162_rn(o0, o1);
        __nv_bfloat162 p1 = __floats2bfloat162_rn(o2, o3);
        uint2 o; o.x = *(unsigned*)&p0; o.y = *(unsigned*)&p1;
        *(uint2*)(d + c) = o;
    }
}

// ---------------- XCA attention, kernel A: partial Gram + sumsq -------------
__global__ __launch_bounds__(256) void attn_gram()
{
    const __nv_bfloat16* qkv16 = (const __nv_bfloat16*)g_big;
    int s = blockIdx.x, h = blockIdx.y, b = blockIdx.z;
    __shared__ float q_s[48][66];
    __shared__ float k_s[48][66];
    int tid = threadIdx.x;
    int td = tid >> 4, te = tid & 15;

    ull acc2[3][3];
#pragma unroll
    for (int i = 0; i < 3; i++)
#pragma unroll
        for (int j = 0; j < 3; j++) acc2[i][j] = 0ULL;
    float qssl = 0.f, kssl = 0.f;

    for (int t = 0; t < 7; t++) {
        int n0 = (s * 7 + t) * 64;
        for (int i = tid; i < 48 * 64; i += 256) {
            int d = i % 48, nn = i / 48;
            size_t base = ((size_t)(b * NTOK + n0 + nn)) * 1152 + h * 48 + d;
            q_s[d][nn] = __bfloat162float(qkv16[base]);
            k_s[d][nn] = __bfloat162float(qkv16[base + 384]);
        }
        __syncthreads();
        if (tid < 48) {
            float tt = 0.f;
#pragma unroll 8
            for (int nn = 0; nn < 64; nn++) { float vv = q_s[tid][nn]; tt += vv * vv; }
            qssl += tt;
        } else if (tid >= 64 && tid < 112) {
            int d = tid - 64;
            float tt = 0.f;
#pragma unroll 8
            for (int nn = 0; nn < 64; nn++) { float vv = k_s[d][nn]; tt += vv * vv; }
            kssl += tt;
        }
#pragma unroll 4
        for (int nn2 = 0; nn2 < 32; nn2++) {
            ull q2[3], k2[3];
#pragma unroll
            for (int i = 0; i < 3; i++)
                q2[i] = *(const ull*)&q_s[td * 3 + i][2 * nn2];
#pragma unroll
            for (int j = 0; j < 3; j++)
                k2[j] = *(const ull*)&k_s[te * 3 + j][2 * nn2];
#pragma unroll
            for (int i = 0; i < 3; i++)
#pragma unroll
                for (int j = 0; j < 3; j++)
                    acc2[i][j] = fma2(q2[i], k2[j], acc2[i][j]);
        }
        __syncthreads();
    }
    int bh = b * 8 + h;
    size_t gbase = ((size_t)(s * 128 + bh)) * 2304;
#pragma unroll
    for (int i = 0; i < 3; i++)
#pragma unroll
        for (int j = 0; j < 3; j++) {
            float lo, hi;
            unpk(lo, hi, acc2[i][j]);
            g_gramP[gbase + (td * 3 + i) * 48 + te * 3 + j] = lo + hi;
        }
    if (tid < 48)                 g_qsqP[(size_t)(s * 128 + bh) * 48 + tid] = qssl;
    if (tid >= 64 && tid < 112)   g_ksqP[(size_t)(s * 128 + bh) * 48 + tid - 64] = kssl;
}

// ---------------- kernel B: reduce partials, softmax, pre-replicate ---------
__global__ __launch_bounds__(64) void attn_soft()
{
    int h = blockIdx.x, b = blockIdx.y;
    int bh = b * 8 + h;
    __shared__ float qn[48], kn[48];
    int tid = threadIdx.x;
    if (tid < 48) {
        float q = 0.f, k = 0.f;
#pragma unroll
        for (int s = 0; s < NSPL; s++) {
            q += g_qsqP[(size_t)(s * 128 + bh) * 48 + tid];
            k += g_ksqP[(size_t)(s * 128 + bh) * 48 + tid];
        }
        qn[tid] = fmaxf(sqrtf(q), 1e-12f);
        kn[tid] = fmaxf(sqrtf(k), 1e-12f);
    }
    __syncthreads();
    if (tid < 48) {
        int r = tid;
        float vals[48];
        float iq = 1.f / qn[r];
#pragma unroll 8
        for (int e = 0; e < 48; e++) {
            float gsum = 0.f;
#pragma unroll
            for (int s = 0; s < NSPL; s++)
                gsum += g_gramP[((size_t)(s * 128 + bh)) * 2304 + r * 48 + e];
            vals[e] = gsum * iq / kn[e];
        }
        float mx = -1e30f;
#pragma unroll 8
        for (int e = 0; e < 48; e++) mx = fmaxf(mx, vals[e]);
        float sm = 0.f;
#pragma unroll 8
        for (int e = 0; e < 48; e++) { vals[e] = expf(vals[e] - mx); sm += vals[e]; }
        float inv = 1.f / sm;
        float2* dst = g_attn2 + (size_t)bh * 2304 + r * 48;
#pragma unroll 8
        for (int e = 0; e < 48; e++) {
            float p = vals[e] * inv;
            dst[e] = make_float2(p, p);
        }
    }
}

// ---------------- kernel C: y = attn @ V, f32x2, 2 tokens/lane --------------
__global__ __launch_bounds__(256) void attn_apply()
{
    const __nv_bfloat16* qkv16 = (const __nv_bfloat16*)g_big;
    int s = blockIdx.x, h = blockIdx.y, b = blockIdx.z;
    __shared__ float2 a2s[2304];
    int tid = threadIdx.x, lane = tid & 31, wid = tid >> 5;
    const float2* gsrc = g_attn2 + (size_t)(b * 8 + h) * 2304;
    for (int i = tid; i < 2304; i += 256) a2s[i] = gsrc[i];
    __syncthreads();

    int wt = s * 8 + wid;
    if (wt >= 49) return;
    int tA = wt * 64 + lane, tB = tA + 32;

    const uint4* vpA = (const uint4*)(qkv16 + ((size_t)(b * NTOK + tA)) * 1152 + 768 + h * 48);
    const uint4* vpB = (const uint4*)(qkv16 + ((size_t)(b * NTOK + tB)) * 1152 + 768 + h * 48);
    ull v2[48];
#pragma unroll
    for (int i = 0; i < 6; i++) {
        uint4 ta = vpA[i], tb = vpB[i];
        unsigned wa[4] = { ta.x, ta.y, ta.z, ta.w };
        unsigned wb[4] = { tb.x, tb.y, tb.z, tb.w };
#pragma unroll
        for (int q = 0; q < 4; q++) {
            float2 fa = __bfloat1622float2(*(__nv_bfloat162*)&wa[q]);
            float2 fb = __bfloat1622float2(*(__nv_bfloat162*)&wb[q]);
            v2[i * 8 + q * 2 + 0] = pk(fa.x, fb.x);
            v2[i * 8 + q * 2 + 1] = pk(fa.y, fb.y);
        }
    }

#pragma unroll
    for (int half = 0; half < 2; half++) {
        float oA[24], oB[24];
#pragma unroll
        for (int d = 0; d < 24; d++) {
            int dd = half * 24 + d;
            ull acc = 0ULL;
            const longlong2* ap = (const longlong2*)&a2s[dd * 48];
#pragma unroll
            for (int e2 = 0; e2 < 24; e2++) {
                longlong2 av = ap[e2];
                acc = fma2((ull)av.x, v2[2 * e2], acc);
                acc = fma2((ull)av.y, v2[2 * e2 + 1], acc);
            }
            unpk(oA[d], oB[d], acc);
        }
        __nv_bfloat16* pA = g_att16 + ((size_t)(b * NTOK + tA)) * CDIM + h * 48 + half * 24;
        __nv_bfloat16* pB = g_att16 + ((size_t)(b * NTOK + tB)) * CDIM + h * 48 + half * 24;
        unsigned wA[12], wB[12];
#pragma unroll
        for (int j = 0; j < 12; j++) {
            __nv_bfloat162 xa = __floats2bfloat162_rn(oA[2 * j], oA[2 * j + 1]);
            __nv_bfloat162 xb = __floats2bfloat162_rn(oB[2 * j], oB[2 * j + 1]);
            wA[j] = *(unsigned*)&xa; wB[j] = *(unsigned*)&xb;
        }
#pragma unroll
        for (int j = 0; j < 3; j++) {
            uint4 oa; oa.x = wA[4*j]; oa.y = wA[4*j+1]; oa.z = wA[4*j+2]; oa.w = wA[4*j+3];
            uint4 ob; ob.x = wB[4*j]; ob.y = wB[4*j+1]; ob.z = wB[4*j+2]; ob.w = wB[4*j+3];
            ((uint4*)pA)[j] = oa;
            ((uint4*)pB)[j] = ob;
        }
    }
}

// ---------------------------------------------------------------------------
extern "C" void kernel_launch(void* const* d_in, const int* in_sizes, int n_in,
                              void* d_out, int out_size)
{
    const float* x       = (const float*)d_in[0];
    const float* dw_w0   = (const float*)d_in[1];
    const float* dw_b0   = (const float*)d_in[2];
    const float* dw_w1   = (const float*)d_in[3];
    const float* dw_b1   = (const float*)d_in[4];
    const float* ln1_g   = (const float*)d_in[5];
    const float* ln1_b   = (const float*)d_in[6];
    const float* qkv_w   = (const float*)d_in[7];
    const float* proj_w  = (const float*)d_in[8];
    const float* proj_b  = (const float*)d_in[9];
    const float* ln2_g   = (const float*)d_in[10];
    const float* ln2_b   = (const float*)d_in[11];
    const float* mlp1_dw = (const float*)d_in[12];
    const float* mlp1_uw = (const float*)d_in[13];
    const float* mlp1_ub = (const float*)d_in[14];
    const float* mlp2_dw = (const float*)d_in[15];
    const float* mlp2_uw = (const float*)d_in[16];
    const float* mlp2_ub = (const float*)d_in[17];
    float* out = (float*)d_out;

    float *big, *s1, *s2, *xf, *xf2;
    __nv_bfloat16 *y16, *att16, *t116, *t216, *h16;
    __nv_bfloat16 *wq, *wp, *w1d, *w1u, *w2d, *w2u;
    cudaGetSymbolAddress((void**)&big,  g_big);
    cudaGetSymbolAddress((void**)&s1,   g_s1);
    cudaGetSymbolAddress((void**)&s2,   g_s2);
    cudaGetSymbolAddress((void**)&xf,   g_xf);
    cudaGetSymbolAddress((void**)&xf2,  g_xf2);
    cudaGetSymbolAddress((void**)&y16,  g_y16);
    cudaGetSymbolAddress((void**)&att16,g_att16);
    cudaGetSymbolAddress((void**)&t116, g_t116);
    cudaGetSymbolAddress((void**)&t216, g_t216);
    cudaGetSymbolAddress((void**)&h16,  g_h16);
    cudaGetSymbolAddress((void**)&wq,   g_wq);
    cudaGetSymbolAddress((void**)&wp,   g_wp);
    cudaGetSymbolAddress((void**)&w1d,  g_w1d);
    cudaGetSymbolAddress((void**)&w1u,  g_w1u);
    cudaGetSymbolAddress((void**)&w2d,  g_w2d);
    cudaGetSymbolAddress((void**)&w2u,  g_w2u);
    __nv_bfloat16* qkv16 = (__nv_bfloat16*)big;

    wtrans_all<<<(WT5 + 255) / 256, 256>>>(qkv_w, proj_w, mlp1_dw, mlp1_uw,
                                           mlp2_dw, mlp2_uw);

    int nconv = Bsz * SPLIT * NTOK;
    int cblk = (nconv + 255) / 256;

    dwconv_kernel<<<cblk, 256>>>(x, (long)CDIM * NTOK,
                                 x + (size_t)SPLIT * NTOK, (long)CDIM * NTOK,
                                 dw_w0, dw_b0, s1);
    dwconv_kernel<<<cblk, 256>>>(s1, (long)SPLIT * NTOK,
                                 x + (size_t)2 * SPLIT * NTOK, (long)CDIM * NTOK,
                                 dw_w1, dw_b1, s2);

    assemble_kernel<<<dim3(98, 12, Bsz), dim3(32, 8)>>>(x);

    // LN1 (warp-per-token)
    ln_warp<<<TOKS / 8, 256>>>(xf, y16, ln1_g, ln1_b);

    // qkv = y @ qkv_w (bf16 out into g_big alias)
    bgemm128<<<dim3(1152/128, TOKS/128), 256>>>(y16, wq, nullptr, qkv16,
                                                TOKS, 1152, 384, nullptr, nullptr, 0);

    // attention: gram partials -> softmax -> apply
    attn_gram<<<dim3(NSPL, NHEAD, Bsz), 256>>>();
    attn_soft<<<dim3(NHEAD, Bsz), 64>>>();
    attn_apply<<<dim3(NSPL, NHEAD, Bsz), 256>>>();

    // xf2 = x_flat + att @ proj_w + proj_b  (residual read from NCHW sources)
    bgemm128_resnchw<<<dim3(384/128, TOKS/128), 256>>>(att16, wp, xf2,
                                                       TOKS, 384, 384, proj_b,
                                                       x, s1, s2);

    // LN2 (warp-per-token)
    ln_warp<<<TOKS / 8, 256>>>(xf2, y16, ln2_g, ln2_b);

    bgemm<<<dim3(192/64, TOKS/128), 256>>>(y16, w1d, nullptr, t116,
                                           TOKS, 192, 384, nullptr, nullptr, 0);
    bgemm128<<<dim3(1536/128, TOKS/128), 256>>>(t116, w1u, nullptr, h16,
                                                TOKS, 1536, 192, mlp1_ub, nullptr, 1);
    bgemm<<<dim3(192/64, TOKS/128), 256>>>(h16, w2d, nullptr, t216,
                                           TOKS, 192, 1536, nullptr, nullptr, 0);
    // final: out(NCHW) = xf2 + t2 @ mlp2_uw + b, fused transpose
    bgemm128_nchw<<<dim3(384/128, TOKS/128), 256>>>(t216, w2u, out,
                                                    TOKS, 384, 192, mlp2_ub, xf2);

    (void)in_sizes; (void)n_in; (void)out_size;
}